// round 1
// baseline (speedup 1.0000x reference)
#include <cuda_runtime.h>
#include <cuda_bf16.h>
#include <cstdint>

// Problem constants
#define B_WIN 512      // batch*windows
#define NTOK  256      // tokens per window
#define CDIM  256      // channels
#define HEADS 8
#define DHEAD 32
#define NW    256      // windows per image
#define MROWS (B_WIN * NTOK)   // 131072 GEMM rows

// ---------------------------------------------------------------------------
// Scratch (static device globals; no allocation allowed)
// ---------------------------------------------------------------------------
__device__ float g_Q[B_WIN * HEADS * NTOK * DHEAD];   // (b,h,n,d)
__device__ float g_K[B_WIN * HEADS * NTOK * DHEAD];
__device__ float g_V[B_WIN * HEADS * NTOK * DHEAD];
__device__ float g_O[B_WIN * NTOK * CDIM];            // (b,n,c)

// ---------------------------------------------------------------------------
// SGEMM: C = A(M x 256) @ W(256 x Ncols) + bias, 128x128x8 tiles, 256 threads,
// 8x8 per-thread register tile, register-prefetch double buffering.
// MODE 0: plain row-major out0[row*Ncols+col]
// MODE 1: Q scatter -> (b,h,n,d)
// MODE 2: KV split scatter -> K=(out0), V=(out1), each (b,h,n,d)
// ---------------------------------------------------------------------------
template<int MODE>
__global__ void __launch_bounds__(256, 2) gemm_kernel(
    const float* __restrict__ A, const float* __restrict__ W,
    const float* __restrict__ bias,
    float* __restrict__ out0, float* __restrict__ out1, int Ncols)
{
    __shared__ float As[8][132];
    __shared__ float Ws[8][132];

    const int t    = threadIdx.x;
    const int row0 = blockIdx.y * 128;
    const int col0 = blockIdx.x * 128;

    const int ar = t >> 1;          // A tile row 0..127
    const int ak = (t & 1) * 4;     // A tile k 0 or 4
    const int wk = t >> 5;          // W tile k 0..7
    const int wc = (t & 31) * 4;    // W tile col 0..124

    const float* Aptr = A + (size_t)(row0 + ar) * 256 + ak;
    const float* Wptr = W + (size_t)wk * Ncols + col0 + wc;

    float4 ra = *(const float4*)Aptr;
    float4 rw = *(const float4*)Wptr;

    float acc[8][8];
#pragma unroll
    for (int i = 0; i < 8; ++i)
#pragma unroll
        for (int j = 0; j < 8; ++j) acc[i][j] = 0.f;

    const int ty = t >> 4;   // 0..15
    const int tx = t & 15;   // 0..15

    for (int it = 0; it < 32; ++it) {
        As[ak + 0][ar] = ra.x;
        As[ak + 1][ar] = ra.y;
        As[ak + 2][ar] = ra.z;
        As[ak + 3][ar] = ra.w;
        *(float4*)&Ws[wk][wc] = rw;
        __syncthreads();
        if (it < 31) {
            ra = *(const float4*)(Aptr + (it + 1) * 8);
            rw = *(const float4*)(Wptr + (size_t)(it + 1) * 8 * Ncols);
        }
#pragma unroll
        for (int kk = 0; kk < 8; ++kk) {
            float af[8], bf[8];
            *(float4*)&af[0] = *(float4*)&As[kk][ty * 8];
            *(float4*)&af[4] = *(float4*)&As[kk][ty * 8 + 4];
            *(float4*)&bf[0] = *(float4*)&Ws[kk][tx * 8];
            *(float4*)&bf[4] = *(float4*)&Ws[kk][tx * 8 + 4];
#pragma unroll
            for (int i = 0; i < 8; ++i)
#pragma unroll
                for (int j = 0; j < 8; ++j)
                    acc[i][j] = fmaf(af[i], bf[j], acc[i][j]);
        }
        __syncthreads();
    }

    // epilogue: bias + scatter
    float bf8[8];
    *(float4*)&bf8[0] = *(const float4*)&bias[col0 + tx * 8];
    *(float4*)&bf8[4] = *(const float4*)&bias[col0 + tx * 8 + 4];

#pragma unroll
    for (int i = 0; i < 8; ++i) {
        const int row = row0 + ty * 8 + i;
#pragma unroll
        for (int jj = 0; jj < 8; jj += 4) {
            const int col = col0 + tx * 8 + jj;
            float4 v;
            v.x = acc[i][jj + 0] + bf8[jj + 0];
            v.y = acc[i][jj + 1] + bf8[jj + 1];
            v.z = acc[i][jj + 2] + bf8[jj + 2];
            v.w = acc[i][jj + 3] + bf8[jj + 3];
            if (MODE == 0) {
                *(float4*)&out0[(size_t)row * Ncols + col] = v;
            } else {
                int cc = (MODE == 2) ? (col & 255) : col;
                float* dst = (MODE == 2 && col >= 256) ? out1 : out0;
                const int b = row >> 8, n = row & 255;
                const int head = cc >> 5, dd = cc & 31;
                size_t idx = (((size_t)(b * HEADS + head) * NTOK + n) << 5) + dd;
                *(float4*)&dst[idx] = v;
            }
        }
    }
}

// ---------------------------------------------------------------------------
// Attention: one CTA per (b,h). SMEM: q row-major, K^T/V^T for vectorized
// reads, per-warp P buffer. 8 warps x 4 passes x 8 rows.
// ---------------------------------------------------------------------------
#define ATT_SMEM ((8192 + 8192 + 32 * 260 + 8 * 2048) * 4)

__global__ void __launch_bounds__(256, 1) attn_kernel(
    const float* __restrict__ Q, const float* __restrict__ K,
    const float* __restrict__ V, const float* __restrict__ mask,
    float* __restrict__ O)
{
    extern __shared__ float sm[];
    float* qs = sm;                  // [256][32]
    float* kT = sm + 8192;           // [32][256]
    float* vT = sm + 16384;          // [32][260] (pad)
    float* ps = sm + 16384 + 32 * 260; // [8 warps][8 rows][256]

    const int bh = blockIdx.x;
    const int b  = bh >> 3;
    const int h  = bh & 7;
    const int w  = b & (NW - 1);
    const size_t base = (size_t)bh * (NTOK * DHEAD);
    const int tid = threadIdx.x;

    {
        const float4* Q4 = (const float4*)(Q + base);
        const float4* K4 = (const float4*)(K + base);
        const float4* V4 = (const float4*)(V + base);
#pragma unroll
        for (int ii = 0; ii < 8; ++ii) {
            const int i = tid + ii * 256;          // float4 index, 2048 total
            const int n = i >> 3;
            const int d0 = (i & 7) << 2;
            float4 qv = Q4[i];
            ((float4*)qs)[i] = qv;
            float4 kv = K4[i];
            kT[(d0 + 0) * 256 + n] = kv.x;
            kT[(d0 + 1) * 256 + n] = kv.y;
            kT[(d0 + 2) * 256 + n] = kv.z;
            kT[(d0 + 3) * 256 + n] = kv.w;
            float4 vv = V4[i];
            vT[(d0 + 0) * 260 + n] = vv.x;
            vT[(d0 + 1) * 260 + n] = vv.y;
            vT[(d0 + 2) * 260 + n] = vv.z;
            vT[(d0 + 3) * 260 + n] = vv.w;
        }
    }
    __syncthreads();

    const int warp = tid >> 5, lane = tid & 31;
    float* psw = ps + warp * 2048;
    const float* maskw = mask + (size_t)w * (NTOK * NTOK);
    const float scale = 0.17677669529663687f;   // 1/sqrt(32)
    float* Obase = O + ((size_t)b * NTOK) * CDIM + h * DHEAD + lane;

    for (int pass = 0; pass < 4; ++pass) {
        const int row0 = warp * 32 + pass * 8;

        // prefetch mask tile into registers (hidden under the QK loop)
        float mrg[8][8];
#pragma unroll
        for (int r = 0; r < 8; ++r) {
            const float* mp = maskw + (size_t)(row0 + r) * NTOK + lane * 8;
            float4 a = *(const float4*)mp;
            float4 c = *(const float4*)(mp + 4);
            mrg[r][0] = a.x; mrg[r][1] = a.y; mrg[r][2] = a.z; mrg[r][3] = a.w;
            mrg[r][4] = c.x; mrg[r][5] = c.y; mrg[r][6] = c.z; mrg[r][7] = c.w;
        }

        float s[8][8];
#pragma unroll
        for (int r = 0; r < 8; ++r)
#pragma unroll
            for (int i = 0; i < 8; ++i) s[r][i] = 0.f;

        // S[r][lane*8+i] = q[row0+r] . k[lane*8+i]
#pragma unroll 8
        for (int d = 0; d < 32; ++d) {
            float kf[8];
            *(float4*)&kf[0] = *(const float4*)&kT[d * 256 + lane * 8];
            *(float4*)&kf[4] = *(const float4*)&kT[d * 256 + lane * 8 + 4];
#pragma unroll
            for (int r = 0; r < 8; ++r) {
                const float qv = qs[(row0 + r) * 32 + d];
#pragma unroll
                for (int i = 0; i < 8; ++i)
                    s[r][i] = fmaf(qv, kf[i], s[r][i]);
            }
        }

        // softmax rows (store un-normalized exp to SMEM, keep 1/sum in regs)
        float rinv[8];
#pragma unroll
        for (int r = 0; r < 8; ++r) {
            float mx = -3.4e38f;
#pragma unroll
            for (int i = 0; i < 8; ++i) {
                const float v = fmaf(s[r][i], scale, mrg[r][i]);
                s[r][i] = v;
                mx = fmaxf(mx, v);
            }
#pragma unroll
            for (int off = 16; off; off >>= 1)
                mx = fmaxf(mx, __shfl_xor_sync(0xffffffffu, mx, off));
            float sum = 0.f;
#pragma unroll
            for (int i = 0; i < 8; ++i) {
                const float e = __expf(s[r][i] - mx);
                sum += e;
                psw[r * 256 + lane * 8 + i] = e;
            }
#pragma unroll
            for (int off = 16; off; off >>= 1)
                sum += __shfl_xor_sync(0xffffffffu, sum, off);
            rinv[r] = 1.0f / sum;
        }
        __syncwarp();

        // O[row][d=lane] = (1/sum) * sum_j P[row][j] * V[j][lane]
        float o[8] = {0.f, 0.f, 0.f, 0.f, 0.f, 0.f, 0.f, 0.f};
#pragma unroll 4
        for (int jc = 0; jc < 256; jc += 4) {
            const float4 vv = *(const float4*)&vT[lane * 260 + jc];
#pragma unroll
            for (int r = 0; r < 8; ++r) {
                const float4 pv = *(const float4*)&psw[r * 256 + jc];
                float acc = fmaf(pv.x, vv.x, fmaf(pv.y, vv.y,
                            fmaf(pv.z, vv.z, pv.w * vv.w)));
                o[r] += acc;
            }
        }
#pragma unroll
        for (int r = 0; r < 8; ++r)
            Obase[(size_t)(row0 + r) * CDIM] = o[r] * rinv[r];
        __syncwarp();
    }
}

// ---------------------------------------------------------------------------
// Host launcher
// ---------------------------------------------------------------------------
extern "C" void kernel_launch(void* const* d_in, const int* in_sizes, int n_in,
                              void* d_out, int out_size)
{
    const float* x    = (const float*)d_in[0];
    const float* mask = (const float*)d_in[1];
    const float* Wq   = (const float*)d_in[2];
    const float* bq   = (const float*)d_in[3];
    const float* Wkv  = (const float*)d_in[4];
    const float* bkv  = (const float*)d_in[5];
    const float* Wp   = (const float*)d_in[6];
    const float* bp   = (const float*)d_in[7];
    float* out = (float*)d_out;

    void *pQ, *pK, *pV, *pO;
    cudaGetSymbolAddress(&pQ, g_Q);
    cudaGetSymbolAddress(&pK, g_K);
    cudaGetSymbolAddress(&pV, g_V);
    cudaGetSymbolAddress(&pO, g_O);
    float* Qb = (float*)pQ;
    float* Kb = (float*)pK;
    float* Vb = (float*)pV;
    float* Ob = (float*)pO;

    cudaFuncSetAttribute(attn_kernel,
                         cudaFuncAttributeMaxDynamicSharedMemorySize, ATT_SMEM);

    dim3 blk(256);
    // Q projection: x @ Wq + bq -> (b,h,n,d)
    gemm_kernel<1><<<dim3(2, MROWS / 128), blk>>>(x, Wq, bq, Qb, nullptr, 256);
    // KV projection: x @ Wkv + bkv -> K,V (b,h,n,d)
    gemm_kernel<2><<<dim3(4, MROWS / 128), blk>>>(x, Wkv, bkv, Kb, Vb, 512);
    // attention per (b,h)
    attn_kernel<<<B_WIN * HEADS, blk, ATT_SMEM>>>(Qb, Kb, Vb, mask, Ob);
    // output projection: O @ Wp + bp -> out
    gemm_kernel<0><<<dim3(2, MROWS / 128), blk>>>(Ob, Wp, bp, out, nullptr, 256);
}